// round 3
// baseline (speedup 1.0000x reference)
#include <cuda_runtime.h>
#include <math.h>

#define N_TOK 1024
#define Dm 512
#define Kf 128
#define Sq 512
#define DK 64

typedef unsigned long long ull;

// ---------------- packed f32x2 helpers --------------------------------------
__device__ __forceinline__ ull F2FMA(ull a, ull b, ull c) {
    ull r; asm("fma.rn.f32x2 %0, %1, %2, %3;" : "=l"(r) : "l"(a), "l"(b), "l"(c));
    return r;
}
__device__ __forceinline__ ull f2pack(float x, float y) {
    return (ull)__float_as_uint(x) | ((ull)__float_as_uint(y) << 32);
}
__device__ __forceinline__ float f2sum(ull v) {
    return __uint_as_float((unsigned)v) + __uint_as_float((unsigned)(v >> 32));
}
#define F2NEG1 0xBF800000BF800000ULL
#define F2ABSM 0x7FFFFFFF7FFFFFFFULL

// ---------------- scratch ---------------------------------------------------
__device__ float g_feat[(N_TOK + 4 * Dm) * Kf];
__device__ float g_R[N_TOK + 4 * Dm];      // row relu-sums of feat
__device__ float g_Rcf[N_TOK];             // row relu-sums of cf
__device__ float g_QKV[3 * N_TOK * Dm];
__device__ float g_scores[16 * Sq * Sq];
__device__ float g_ctx[N_TOK * Dm];
__device__ float g_cf[N_TOK * Kf];

// ---------------- fused feature GEMM: feat = [x;Pq;Pk;Pv;Po] @ omega --------
__global__ __launch_bounds__(256) void feat_gemm(
    const float* __restrict__ x,  const float* __restrict__ Pq,
    const float* __restrict__ Pk, const float* __restrict__ Pv,
    const float* __restrict__ Po, const float* __restrict__ omega,
    float* __restrict__ feat)
{
    __shared__ float As[32][68];
    __shared__ float Bs[32][68];
    int tx = threadIdx.x, ty = threadIdx.y;
    int tid = ty * 16 + tx;
    int bm = blockIdx.y * 64, bn = blockIdx.x * 64;

    const float* A;
    int row0;
    if (bm < N_TOK) { A = x; row0 = bm; }
    else {
        int s = (bm - N_TOK) >> 9;
        const float* Ps[4] = {Pq, Pk, Pv, Po};
        A = Ps[s]; row0 = (bm - N_TOK) & 511;
    }

    float acc[4][4] = {};
    for (int k0 = 0; k0 < Dm; k0 += 32) {
#pragma unroll
        for (int l = 0; l < 8; l++) {
            int e = tid + l * 256;
            int i = e >> 5, j = e & 31;
            As[j][i] = A[(size_t)(row0 + i) * Dm + k0 + j];
        }
#pragma unroll
        for (int l = 0; l < 8; l++) {
            int e = tid + l * 256;
            int kk = e >> 6, j = e & 63;
            Bs[kk][j] = omega[(size_t)(k0 + kk) * Kf + bn + j];
        }
        __syncthreads();
#pragma unroll
        for (int k = 0; k < 32; k++) {
            float4 a4 = *(const float4*)&As[k][ty * 4];
            float4 b4 = *(const float4*)&Bs[k][tx * 4];
            float av[4] = {a4.x, a4.y, a4.z, a4.w};
            float bv[4] = {b4.x, b4.y, b4.z, b4.w};
#pragma unroll
            for (int i = 0; i < 4; i++)
#pragma unroll
                for (int j = 0; j < 4; j++)
                    acc[i][j] = fmaf(av[i], bv[j], acc[i][j]);
        }
        __syncthreads();
    }
#pragma unroll
    for (int i = 0; i < 4; i++)
#pragma unroll
        for (int j = 0; j < 4; j++)
            feat[(size_t)(bm + ty * 4 + i) * Kf + bn + tx * 4 + j] = acc[i][j];
}

// ---------------- plain GEMM for ctx @ omega --------------------------------
__global__ __launch_bounds__(256) void gemm_nn(
    const float* __restrict__ A, const float* __restrict__ B,
    float* __restrict__ C, int M, int N, int K, int lda, int ldb, int ldc)
{
    __shared__ float As[32][68];
    __shared__ float Bs[32][68];
    int tx = threadIdx.x, ty = threadIdx.y;
    int tid = ty * 16 + tx;
    int bm = blockIdx.y * 64, bn = blockIdx.x * 64;
    float acc[4][4] = {};
    for (int k0 = 0; k0 < K; k0 += 32) {
#pragma unroll
        for (int l = 0; l < 8; l++) {
            int e = tid + l * 256;
            int i = e >> 5, j = e & 31;
            As[j][i] = A[(size_t)(bm + i) * lda + k0 + j];
        }
#pragma unroll
        for (int l = 0; l < 8; l++) {
            int e = tid + l * 256;
            int kk = e >> 6, j = e & 63;
            Bs[kk][j] = B[(size_t)(k0 + kk) * ldb + bn + j];
        }
        __syncthreads();
#pragma unroll
        for (int k = 0; k < 32; k++) {
            float4 a4 = *(const float4*)&As[k][ty * 4];
            float4 b4 = *(const float4*)&Bs[k][tx * 4];
            float av[4] = {a4.x, a4.y, a4.z, a4.w};
            float bv[4] = {b4.x, b4.y, b4.z, b4.w};
#pragma unroll
            for (int i = 0; i < 4; i++)
#pragma unroll
                for (int j = 0; j < 4; j++)
                    acc[i][j] = fmaf(av[i], bv[j], acc[i][j]);
        }
        __syncthreads();
    }
#pragma unroll
    for (int i = 0; i < 4; i++)
#pragma unroll
        for (int j = 0; j < 4; j++)
            C[(size_t)(bm + ty * 4 + i) * ldc + bn + tx * 4 + j] = acc[i][j];
}

// ---------------- row relu-sums: R[i] = sum_k relu(f[i][k]), 128 cols -------
__global__ __launch_bounds__(256) void rowrelu(const float* __restrict__ f,
                                               float* __restrict__ R)
{
    int row = blockIdx.x * 8 + threadIdx.y;
    int lane = threadIdx.x;
    float4 v = ((const float4*)(f + (size_t)row * Kf))[lane];
    float s = fmaxf(v.x, 0.f) + fmaxf(v.y, 0.f) + fmaxf(v.z, 0.f) + fmaxf(v.w, 0.f);
#pragma unroll
    for (int o = 16; o; o >>= 1) s += __shfl_xor_sync(0xffffffffu, s, o);
    if (lane == 0) R[row] = s;
}

// ---------------- packed Tversky tile ---------------------------------------
// acc_ij = sum_k[ th*relu(a)relu(p) + (al/2)xm*p + (be/2)a*pm
//                 - ((al/2)xm + (be/2)pm)*|a-p| ]
// out = acc - (al/2)*Rx[i] - (be/2)*Rp[j]
__device__ __forceinline__ void tversky_tile_pk(
    const float* __restrict__ xf, const float* __restrict__ pf,
    const float* __restrict__ Rx, const float* __restrict__ Rp,
    float th, float al, float be, int bn, int bo,
    float* __restrict__ out, int ldo)
{
    __shared__ ull sa[4][66], sA1[4][66], sA2[4][66], sxw[4][66];
    __shared__ ull sp[4][66], sB1[4][66], sB2[4][66], spw[4][66];
    const float ha = 0.5f * al, hb = 0.5f * be;
    int tx = threadIdx.x, ty = threadIdx.y;
    int tid = ty * 16 + tx;
    int fkk = tid & 3, fi = tid >> 2;          // fill slot: kk 0..3, i 0..63
    ull acc[4][4] = {};

    for (int c = 0; c < 16; c++) {
        int k0 = c * 8;
        {
            float2 a2 = *(const float2*)&xf[(size_t)(bn + fi) * Kf + k0 + 2 * fkk];
            sa [fkk][fi] = f2pack(a2.x, a2.y);
            sA1[fkk][fi] = f2pack(th * fmaxf(a2.x, 0.f), th * fmaxf(a2.y, 0.f));
            sA2[fkk][fi] = f2pack(a2.x > 0.f ? ha : 0.f, a2.y > 0.f ? ha : 0.f);
            sxw[fkk][fi] = f2pack(a2.x > 0.f ? -ha : 0.f, a2.y > 0.f ? -ha : 0.f);
            float2 p2 = *(const float2*)&pf[(size_t)(bo + fi) * Kf + k0 + 2 * fkk];
            sp [fkk][fi] = f2pack(p2.x, p2.y);
            sB1[fkk][fi] = f2pack(fmaxf(p2.x, 0.f), fmaxf(p2.y, 0.f));
            sB2[fkk][fi] = f2pack(p2.x > 0.f ? hb : 0.f, p2.y > 0.f ? hb : 0.f);
            spw[fkk][fi] = f2pack(p2.x > 0.f ? -hb : 0.f, p2.y > 0.f ? -hb : 0.f);
        }
        __syncthreads();
#pragma unroll
        for (int kk = 0; kk < 4; kk++) {
            ulonglong2 va0 = *(const ulonglong2*)&sa [kk][ty * 4];
            ulonglong2 va1 = *(const ulonglong2*)&sa [kk][ty * 4 + 2];
            ulonglong2 vA10 = *(const ulonglong2*)&sA1[kk][ty * 4];
            ulonglong2 vA11 = *(const ulonglong2*)&sA1[kk][ty * 4 + 2];
            ulonglong2 vA20 = *(const ulonglong2*)&sA2[kk][ty * 4];
            ulonglong2 vA21 = *(const ulonglong2*)&sA2[kk][ty * 4 + 2];
            ulonglong2 vxw0 = *(const ulonglong2*)&sxw[kk][ty * 4];
            ulonglong2 vxw1 = *(const ulonglong2*)&sxw[kk][ty * 4 + 2];
            ulonglong2 vp0 = *(const ulonglong2*)&sp [kk][tx * 4];
            ulonglong2 vp1 = *(const ulonglong2*)&sp [kk][tx * 4 + 2];
            ulonglong2 vB10 = *(const ulonglong2*)&sB1[kk][tx * 4];
            ulonglong2 vB11 = *(const ulonglong2*)&sB1[kk][tx * 4 + 2];
            ulonglong2 vB20 = *(const ulonglong2*)&sB2[kk][tx * 4];
            ulonglong2 vB21 = *(const ulonglong2*)&sB2[kk][tx * 4 + 2];
            ulonglong2 vpw0 = *(const ulonglong2*)&spw[kk][tx * 4];
            ulonglong2 vpw1 = *(const ulonglong2*)&spw[kk][tx * 4 + 2];
            ull ra[4]  = {va0.x, va0.y, va1.x, va1.y};
            ull rA1[4] = {vA10.x, vA10.y, vA11.x, vA11.y};
            ull rA2[4] = {vA20.x, vA20.y, vA21.x, vA21.y};
            ull rxw[4] = {vxw0.x, vxw0.y, vxw1.x, vxw1.y};
            ull rp[4]  = {vp0.x, vp0.y, vp1.x, vp1.y};
            ull rB1[4] = {vB10.x, vB10.y, vB11.x, vB11.y};
            ull rB2[4] = {vB20.x, vB20.y, vB21.x, vB21.y};
            ull rpw[4] = {vpw0.x, vpw0.y, vpw1.x, vpw1.y};
#pragma unroll
            for (int i = 0; i < 4; i++)
#pragma unroll
                for (int j = 0; j < 4; j++) {
                    ull d  = F2FMA(rp[j], F2NEG1, ra[i]);   // a - p (packed)
                    ull ad = d & F2ABSM;                    // |a - p|
                    ull t = acc[i][j];
                    t = F2FMA(rA1[i], rB1[j], t);
                    t = F2FMA(rA2[i], rp[j], t);
                    t = F2FMA(ra[i],  rB2[j], t);
                    t = F2FMA(rxw[i], ad, t);
                    t = F2FMA(rpw[j], ad, t);
                    acc[i][j] = t;
                }
        }
        __syncthreads();
    }
    float rx[4], rpj[4];
#pragma unroll
    for (int i = 0; i < 4; i++) rx[i] = Rx[bn + ty * 4 + i];
#pragma unroll
    for (int j = 0; j < 4; j++) rpj[j] = Rp[bo + tx * 4 + j];
#pragma unroll
    for (int i = 0; i < 4; i++)
#pragma unroll
        for (int j = 0; j < 4; j++)
            out[(size_t)(bn + ty * 4 + i) * ldo + bo + tx * 4 + j] =
                f2sum(acc[i][j]) - ha * rx[i] - hb * rpj[j];
}

__global__ __launch_bounds__(256) void tversky_qkv(
    const float* __restrict__ feat, const float* __restrict__ R,
    const float* __restrict__ tab, float* __restrict__ qkv)
{
    int z = blockIdx.z;
    const float* xf = feat;
    const float* pf = feat + (size_t)(N_TOK + z * Dm) * Kf;
    const float* Rx = R;
    const float* Rp = R + N_TOK + z * Dm;
    const float* t3 = tab + z * 3;
    float* out = qkv + (size_t)z * N_TOK * Dm;
    tversky_tile_pk(xf, pf, Rx, Rp, t3[0], t3[1], t3[2],
                    blockIdx.y * 64, blockIdx.x * 64, out, Dm);
}

__global__ __launch_bounds__(256) void tversky_out(
    const float* __restrict__ cf, const float* __restrict__ Rcf,
    const float* __restrict__ feat, const float* __restrict__ R,
    const float* __restrict__ tab, float* __restrict__ out)
{
    const float* pf = feat + (size_t)(N_TOK + 3 * Dm) * Kf;
    const float* Rp = R + N_TOK + 3 * Dm;
    tversky_tile_pk(cf, Rcf, pf, Rp, 0.f, 0.f, 0.f, 0, 0, out, Dm);  // placeholder (never used)
}

// NOTE: the placeholder above is wrong-order; define a correct dedicated kernel:
__global__ __launch_bounds__(256) void tversky_out2(
    const float* __restrict__ cf, const float* __restrict__ Rcf,
    const float* __restrict__ feat, const float* __restrict__ R,
    const float* __restrict__ tab, float* __restrict__ out)
{
    const float* pf = feat + (size_t)(N_TOK + 3 * Dm) * Kf;
    const float* Rp = R + N_TOK + 3 * Dm;
    tversky_tile_pk(cf, pf, Rcf, Rp, tab[9], tab[10], tab[11],
                    blockIdx.y * 64, blockIdx.x * 64, out, Dm);
}

// ---------------- scores: S = Q @ K^T / 8, masked (f32x2 over d) ------------
__global__ __launch_bounds__(256) void scores_kernel(
    const float* __restrict__ Q, const float* __restrict__ Km,
    const int* __restrict__ mask, float* __restrict__ scores)
{
    __shared__ ull Qs[32][66];
    __shared__ ull Ks[32][66];
    int z = blockIdx.z;
    int b = z >> 3, h = z & 7;
    const float* Qg = Q  + (size_t)b * Sq * Dm + h * DK;
    const float* Kg = Km + (size_t)b * Sq * Dm + h * DK;
    int bq = blockIdx.y * 64, bk = blockIdx.x * 64;
    int tx = threadIdx.x, ty = threadIdx.y;
    int tid = ty * 16 + tx;
#pragma unroll
    for (int l = 0; l < 8; l++) {
        int e = tid + l * 256;
        int dd = e & 31, m = e >> 5;
        float2 q2 = *(const float2*)&Qg[(size_t)(bq + m) * Dm + 2 * dd];
        float2 k2 = *(const float2*)&Kg[(size_t)(bk + m) * Dm + 2 * dd];
        Qs[dd][m] = f2pack(q2.x, q2.y);
        Ks[dd][m] = f2pack(k2.x, k2.y);
    }
    __syncthreads();
    ull acc[4][4] = {};
#pragma unroll
    for (int dd = 0; dd < 32; dd++) {
        ulonglong2 q0 = *(const ulonglong2*)&Qs[dd][ty * 4];
        ulonglong2 q1 = *(const ulonglong2*)&Qs[dd][ty * 4 + 2];
        ulonglong2 k0 = *(const ulonglong2*)&Ks[dd][tx * 4];
        ulonglong2 k1 = *(const ulonglong2*)&Ks[dd][tx * 4 + 2];
        ull qa[4] = {q0.x, q0.y, q1.x, q1.y};
        ull ka[4] = {k0.x, k0.y, k1.x, k1.y};
#pragma unroll
        for (int i = 0; i < 4; i++)
#pragma unroll
            for (int j = 0; j < 4; j++)
                acc[i][j] = F2FMA(qa[i], ka[j], acc[i][j]);
    }
    float* sout = scores + (size_t)z * Sq * Sq;
    const int* mg = mask + (size_t)b * Sq * Sq;
#pragma unroll
    for (int i = 0; i < 4; i++)
#pragma unroll
        for (int j = 0; j < 4; j++) {
            int q = bq + ty * 4 + i, kk = bk + tx * 4 + j;
            float s = f2sum(acc[i][j]) * 0.125f;
            if (mg[(size_t)q * Sq + kk] == 0) s = -INFINITY;
            sout[(size_t)q * Sq + kk] = s;
        }
}

// ---------------- row softmax over 512 --------------------------------------
__global__ __launch_bounds__(128) void softmax_kernel(float* __restrict__ scores)
{
    __shared__ float red_m[4], red_s[4];
    size_t row = blockIdx.x;
    float* r = scores + row * Sq;
    int t = threadIdx.x;
    float v0 = r[t], v1 = r[t + 128], v2 = r[t + 256], v3 = r[t + 384];
    float m = fmaxf(fmaxf(v0, v1), fmaxf(v2, v3));
#pragma unroll
    for (int o = 16; o; o >>= 1) m = fmaxf(m, __shfl_xor_sync(0xffffffffu, m, o));
    if ((t & 31) == 0) red_m[t >> 5] = m;
    __syncthreads();
    m = fmaxf(fmaxf(red_m[0], red_m[1]), fmaxf(red_m[2], red_m[3]));
    float e0 = expf(v0 - m), e1 = expf(v1 - m), e2 = expf(v2 - m), e3 = expf(v3 - m);
    float s = e0 + e1 + e2 + e3;
#pragma unroll
    for (int o = 16; o; o >>= 1) s += __shfl_xor_sync(0xffffffffu, s, o);
    if ((t & 31) == 0) red_s[t >> 5] = s;
    __syncthreads();
    s = red_s[0] + red_s[1] + red_s[2] + red_s[3];
    float inv = 1.f / s;
    r[t]       = e0 * inv;
    r[t + 128] = e1 * inv;
    r[t + 256] = e2 * inv;
    r[t + 384] = e3 * inv;
}

// ---------------- ctx = attn @ V (per head), f32x2 over k -------------------
__global__ __launch_bounds__(256) void ctx_kernel(
    const float* __restrict__ scores, const float* __restrict__ V,
    float* __restrict__ ctx)
{
    __shared__ ull As[16][66];   // [kk][q]
    __shared__ ull Bs[16][66];   // [kk][d]
    int z = blockIdx.z;
    int b = z >> 3, h = z & 7;
    const float* Ag = scores + (size_t)z * Sq * Sq;
    const float* Vg = V + (size_t)b * Sq * Dm + h * DK;
    int bq = blockIdx.y * 64;
    int tx = threadIdx.x, ty = threadIdx.y;
    int tid = ty * 16 + tx;
    ull acc[4][4] = {};
    for (int k0 = 0; k0 < Sq; k0 += 32) {
#pragma unroll
        for (int l = 0; l < 4; l++) {            // As: 16kk x 64q = 1024 slots
            int e = tid + l * 256;
            int kk = e & 15, q = e >> 4;
            float2 a2 = *(const float2*)&Ag[(size_t)(bq + q) * Sq + k0 + 2 * kk];
            As[kk][q] = f2pack(a2.x, a2.y);
        }
#pragma unroll
        for (int l = 0; l < 4; l++) {            // Bs: 16kk x 64d
            int e = tid + l * 256;
            int d = e & 63, kk = e >> 6;
            float b0 = Vg[(size_t)(k0 + 2 * kk) * Dm + d];
            float b1 = Vg[(size_t)(k0 + 2 * kk + 1) * Dm + d];
            Bs[kk][d] = f2pack(b0, b1);
        }
        __syncthreads();
#pragma unroll
        for (int kk = 0; kk < 16; kk++) {
            ulonglong2 a0 = *(const ulonglong2*)&As[kk][ty * 4];
            ulonglong2 a1 = *(const ulonglong2*)&As[kk][ty * 4 + 2];
            ulonglong2 b0 = *(const ulonglong2*)&Bs[kk][tx * 4];
            ulonglong2 b1 = *(const ulonglong2*)&Bs[kk][tx * 4 + 2];
            ull aa[4] = {a0.x, a0.y, a1.x, a1.y};
            ull bb[4] = {b0.x, b0.y, b1.x, b1.y};
#pragma unroll
            for (int i = 0; i < 4; i++)
#pragma unroll
                for (int j = 0; j < 4; j++)
                    acc[i][j] = F2FMA(aa[i], bb[j], acc[i][j]);
        }
        __syncthreads();
    }
    float* cg = ctx + (size_t)b * Sq * Dm + h * DK;
#pragma unroll
    for (int i = 0; i < 4; i++)
#pragma unroll
        for (int j = 0; j < 4; j++)
            cg[(size_t)(bq + ty * 4 + i) * Dm + tx * 4 + j] = f2sum(acc[i][j]);
}

// ---------------- launch ----------------------------------------------------
extern "C" void kernel_launch(void* const* d_in, const int* in_sizes, int n_in,
                              void* d_out, int out_size)
{
    const float* x     = (const float*)d_in[0];
    const int*   mask  = (const int*)d_in[1];
    const float* omega = (const float*)d_in[2];
    const float* Pq    = (const float*)d_in[3];
    const float* Pk    = (const float*)d_in[4];
    const float* Pv    = (const float*)d_in[5];
    const float* Po    = (const float*)d_in[6];
    const float* tab   = (const float*)d_in[7];
    float* out = (float*)d_out;

    float *p_feat, *p_R, *p_Rcf, *p_qkv, *p_sc, *p_ctx, *p_cf;
    cudaGetSymbolAddress((void**)&p_feat, g_feat);
    cudaGetSymbolAddress((void**)&p_R, g_R);
    cudaGetSymbolAddress((void**)&p_Rcf, g_Rcf);
    cudaGetSymbolAddress((void**)&p_qkv, g_QKV);
    cudaGetSymbolAddress((void**)&p_sc, g_scores);
    cudaGetSymbolAddress((void**)&p_ctx, g_ctx);
    cudaGetSymbolAddress((void**)&p_cf, g_cf);

    float* p_Q = p_qkv;
    float* p_K = p_qkv + (size_t)N_TOK * Dm;
    float* p_V = p_qkv + (size_t)2 * N_TOK * Dm;

    dim3 blk(16, 16);

    // feature maps + row relu-sums
    feat_gemm<<<dim3(2, 48), blk>>>(x, Pq, Pk, Pv, Po, omega, p_feat);
    rowrelu<<<(N_TOK + 4 * Dm) / 8, dim3(32, 8)>>>(p_feat, p_R);

    // Q, K, V projections
    tversky_qkv<<<dim3(8, 16, 3), blk>>>(p_feat, p_R, tab, p_qkv);

    // attention
    scores_kernel<<<dim3(8, 8, 16), blk>>>(p_Q, p_K, mask, p_sc);
    softmax_kernel<<<16 * Sq, 128>>>(p_sc);
    ctx_kernel<<<dim3(1, 8, 16), blk>>>(p_sc, p_V, p_ctx);

    // output projection
    gemm_nn<<<dim3(2, 16), blk>>>(p_ctx, omega, p_cf, N_TOK, Kf, Dm, Dm, Kf, Kf);
    rowrelu<<<N_TOK / 8, dim3(32, 8)>>>(p_cf, p_Rcf);
    tversky_out2<<<dim3(8, 16), blk>>>(p_cf, p_Rcf, p_feat, p_R, tab, out);
}

// round 4
// speedup vs baseline: 1.1572x; 1.1572x over previous
#include <cuda_runtime.h>
#include <math.h>

#define N_TOK 1024
#define Dm 512
#define Kf 128
#define Sq 512
#define DK 64

typedef unsigned long long ull;

// ---------------- packed f32x2 helpers --------------------------------------
__device__ __forceinline__ ull F2FMA(ull a, ull b, ull c) {
    ull r; asm("fma.rn.f32x2 %0, %1, %2, %3;" : "=l"(r) : "l"(a), "l"(b), "l"(c));
    return r;
}
__device__ __forceinline__ ull f2pack(float x, float y) {
    return (ull)__float_as_uint(x) | ((ull)__float_as_uint(y) << 32);
}
__device__ __forceinline__ float f2sum(ull v) {
    return __uint_as_float((unsigned)v) + __uint_as_float((unsigned)(v >> 32));
}
#define F2NEG1 0xBF800000BF800000ULL
#define F2ABSM 0x7FFFFFFF7FFFFFFFULL

// ---------------- scratch ---------------------------------------------------
__device__ float g_feat[(N_TOK + 4 * Dm) * Kf];
__device__ float g_R[N_TOK + 4 * Dm];
__device__ float g_Rcf[N_TOK];
__device__ float g_QKV[3 * N_TOK * Dm];
__device__ float g_scores[16 * Sq * Sq];
__device__ float g_ctx[N_TOK * Dm];
__device__ float g_cf[N_TOK * Kf];

// ---------------- fused feature GEMM: feat = [x;Pq;Pk;Pv;Po] @ omega --------
__global__ __launch_bounds__(256) void feat_gemm(
    const float* __restrict__ x,  const float* __restrict__ Pq,
    const float* __restrict__ Pk, const float* __restrict__ Pv,
    const float* __restrict__ Po, const float* __restrict__ omega,
    float* __restrict__ feat)
{
    __shared__ float As[32][68];
    __shared__ float Bs[32][68];
    int tx = threadIdx.x, ty = threadIdx.y;
    int tid = ty * 16 + tx;
    int bm = blockIdx.y * 64, bn = blockIdx.x * 64;

    const float* A;
    int row0;
    if (bm < N_TOK) { A = x; row0 = bm; }
    else {
        int s = (bm - N_TOK) >> 9;
        const float* Ps[4] = {Pq, Pk, Pv, Po};
        A = Ps[s]; row0 = (bm - N_TOK) & 511;
    }

    float acc[4][4] = {};
    for (int k0 = 0; k0 < Dm; k0 += 32) {
#pragma unroll
        for (int l = 0; l < 8; l++) {
            int e = tid + l * 256;
            int i = e >> 5, j = e & 31;
            As[j][i] = A[(size_t)(row0 + i) * Dm + k0 + j];
        }
#pragma unroll
        for (int l = 0; l < 8; l++) {
            int e = tid + l * 256;
            int kk = e >> 6, j = e & 63;
            Bs[kk][j] = omega[(size_t)(k0 + kk) * Kf + bn + j];
        }
        __syncthreads();
#pragma unroll
        for (int k = 0; k < 32; k++) {
            float4 a4 = *(const float4*)&As[k][ty * 4];
            float4 b4 = *(const float4*)&Bs[k][tx * 4];
            float av[4] = {a4.x, a4.y, a4.z, a4.w};
            float bv[4] = {b4.x, b4.y, b4.z, b4.w};
#pragma unroll
            for (int i = 0; i < 4; i++)
#pragma unroll
                for (int j = 0; j < 4; j++)
                    acc[i][j] = fmaf(av[i], bv[j], acc[i][j]);
        }
        __syncthreads();
    }
#pragma unroll
    for (int i = 0; i < 4; i++)
#pragma unroll
        for (int j = 0; j < 4; j++)
            feat[(size_t)(bm + ty * 4 + i) * Kf + bn + tx * 4 + j] = acc[i][j];
}

// ---------------- plain GEMM for ctx @ omega --------------------------------
__global__ __launch_bounds__(256) void gemm_nn(
    const float* __restrict__ A, const float* __restrict__ B,
    float* __restrict__ C, int M, int N, int K, int lda, int ldb, int ldc)
{
    __shared__ float As[32][68];
    __shared__ float Bs[32][68];
    int tx = threadIdx.x, ty = threadIdx.y;
    int tid = ty * 16 + tx;
    int bm = blockIdx.y * 64, bn = blockIdx.x * 64;
    float acc[4][4] = {};
    for (int k0 = 0; k0 < K; k0 += 32) {
#pragma unroll
        for (int l = 0; l < 8; l++) {
            int e = tid + l * 256;
            int i = e >> 5, j = e & 31;
            As[j][i] = A[(size_t)(bm + i) * lda + k0 + j];
        }
#pragma unroll
        for (int l = 0; l < 8; l++) {
            int e = tid + l * 256;
            int kk = e >> 6, j = e & 63;
            Bs[kk][j] = B[(size_t)(k0 + kk) * ldb + bn + j];
        }
        __syncthreads();
#pragma unroll
        for (int k = 0; k < 32; k++) {
            float4 a4 = *(const float4*)&As[k][ty * 4];
            float4 b4 = *(const float4*)&Bs[k][tx * 4];
            float av[4] = {a4.x, a4.y, a4.z, a4.w};
            float bv[4] = {b4.x, b4.y, b4.z, b4.w};
#pragma unroll
            for (int i = 0; i < 4; i++)
#pragma unroll
                for (int j = 0; j < 4; j++)
                    acc[i][j] = fmaf(av[i], bv[j], acc[i][j]);
        }
        __syncthreads();
    }
#pragma unroll
    for (int i = 0; i < 4; i++)
#pragma unroll
        for (int j = 0; j < 4; j++)
            C[(size_t)(bm + ty * 4 + i) * ldc + bn + tx * 4 + j] = acc[i][j];
}

// ---------------- row relu-sums ---------------------------------------------
__global__ __launch_bounds__(256) void rowrelu(const float* __restrict__ f,
                                               float* __restrict__ R)
{
    int row = blockIdx.x * 8 + threadIdx.y;
    int lane = threadIdx.x;
    float4 v = ((const float4*)(f + (size_t)row * Kf))[lane];
    float s = fmaxf(v.x, 0.f) + fmaxf(v.y, 0.f) + fmaxf(v.z, 0.f) + fmaxf(v.w, 0.f);
#pragma unroll
    for (int o = 16; o; o >>= 1) s += __shfl_xor_sync(0xffffffffu, s, o);
    if (lane == 0) R[row] = s;
}

// ---------------- Tversky 64x64 tile, f32x2, 6 operand planes ---------------
// sim_k = th*ar*pr + ha*am*(p-|d|) + hb*pm*(a-|d|)  (accumulated)
// out = acc - ha*Rx[i] - hb*Rp[j]   with ar=relu(a), am=[a>0], d=a-p.
// Block: 128 threads (16x8). Micro-tile: 8 rows x 4 cols, k packed in pairs.
__device__ __forceinline__ void tversky64(
    const float* __restrict__ xf, const float* __restrict__ pf,
    const float* __restrict__ Rx, const float* __restrict__ Rp,
    float th, float al, float be, int bn, int bo,
    float* __restrict__ out, int ldo)
{
    __shared__ ull sa[8][66], sA1[8][66], sA2[8][66];
    __shared__ ull sp[8][66], sPr[8][66], sB2[8][66];
    const float ha = 0.5f * al, hb = 0.5f * be;
    int tx = threadIdx.x, ty = threadIdx.y;      // 16 x 8
    int tid = ty * 16 + tx;                      // 0..127
    int fkk = tid & 7, fr = tid >> 3;            // fill: kk 0..7, row 0..15
    ull acc[8][4] = {};

    for (int c = 0; c < 8; c++) {                // 8 chunks of 16 k (8 k2)
        int k0 = c * 16;
#pragma unroll
        for (int p = 0; p < 4; p++) {
            int r = fr + p * 16;
            float2 a2 = *(const float2*)&xf[(size_t)(bn + r) * Kf + k0 + 2 * fkk];
            sa [fkk][r] = f2pack(a2.x, a2.y);
            sA1[fkk][r] = f2pack(th * fmaxf(a2.x, 0.f), th * fmaxf(a2.y, 0.f));
            sA2[fkk][r] = f2pack(a2.x > 0.f ? ha : 0.f, a2.y > 0.f ? ha : 0.f);
        }
#pragma unroll
        for (int p = 0; p < 4; p++) {
            int r = fr + p * 16;
            float2 p2 = *(const float2*)&pf[(size_t)(bo + r) * Kf + k0 + 2 * fkk];
            sp [fkk][r] = f2pack(p2.x, p2.y);
            sPr[fkk][r] = f2pack(fmaxf(p2.x, 0.f), fmaxf(p2.y, 0.f));
            sB2[fkk][r] = f2pack(p2.x > 0.f ? hb : 0.f, p2.y > 0.f ? hb : 0.f);
        }
        __syncthreads();
#pragma unroll
        for (int kk = 0; kk < 8; kk++) {
            ull ra[8], rA1[8], rA2[8], rp[4], rPr[4], rB2[4];
#pragma unroll
            for (int i = 0; i < 8; i += 2) {
                ulonglong2 t0 = *(const ulonglong2*)&sa [kk][ty * 8 + i];
                ra[i] = t0.x;  ra[i+1] = t0.y;
                ulonglong2 t1 = *(const ulonglong2*)&sA1[kk][ty * 8 + i];
                rA1[i] = t1.x; rA1[i+1] = t1.y;
                ulonglong2 t2 = *(const ulonglong2*)&sA2[kk][ty * 8 + i];
                rA2[i] = t2.x; rA2[i+1] = t2.y;
            }
#pragma unroll
            for (int j = 0; j < 4; j += 2) {
                ulonglong2 t0 = *(const ulonglong2*)&sp [kk][tx * 4 + j];
                rp[j] = t0.x;  rp[j+1] = t0.y;
                ulonglong2 t1 = *(const ulonglong2*)&sPr[kk][tx * 4 + j];
                rPr[j] = t1.x; rPr[j+1] = t1.y;
                ulonglong2 t2 = *(const ulonglong2*)&sB2[kk][tx * 4 + j];
                rB2[j] = t2.x; rB2[j+1] = t2.y;
            }
#pragma unroll
            for (int i = 0; i < 8; i++)
#pragma unroll
                for (int j = 0; j < 4; j++) {
                    ull d  = F2FMA(rp[j], F2NEG1, ra[i]);   // a - p
                    ull ad = d & F2ABSM;                    // |a - p|
                    ull u  = F2FMA(ad, F2NEG1, rp[j]);      // p - |d|
                    ull v  = F2FMA(ad, F2NEG1, ra[i]);      // a - |d|
                    ull t = acc[i][j];
                    t = F2FMA(rA1[i], rPr[j], t);
                    t = F2FMA(rA2[i], u, t);
                    t = F2FMA(rB2[j], v, t);
                    acc[i][j] = t;
                }
        }
        __syncthreads();
    }
    float rx[8], rpj[4];
#pragma unroll
    for (int i = 0; i < 8; i++) rx[i] = Rx[bn + ty * 8 + i];
#pragma unroll
    for (int j = 0; j < 4; j++) rpj[j] = Rp[bo + tx * 4 + j];
#pragma unroll
    for (int i = 0; i < 8; i++)
#pragma unroll
        for (int j = 0; j < 4; j++)
            out[(size_t)(bn + ty * 8 + i) * ldo + bo + tx * 4 + j] =
                f2sum(acc[i][j]) - ha * rx[i] - hb * rpj[j];
}

__global__ __launch_bounds__(128) void tversky_qkv(
    const float* __restrict__ feat, const float* __restrict__ R,
    const float* __restrict__ tab, float* __restrict__ qkv)
{
    int z = blockIdx.z;
    const float* pf = feat + (size_t)(N_TOK + z * Dm) * Kf;
    const float* Rp = R + N_TOK + z * Dm;
    const float* t3 = tab + z * 3;
    float* out = qkv + (size_t)z * N_TOK * Dm;
    tversky64(feat, pf, R, Rp, t3[0], t3[1], t3[2],
              blockIdx.y * 64, blockIdx.x * 64, out, Dm);
}

__global__ __launch_bounds__(128) void tversky_out(
    const float* __restrict__ cf, const float* __restrict__ Rcf,
    const float* __restrict__ feat, const float* __restrict__ R,
    const float* __restrict__ tab, float* __restrict__ out)
{
    const float* pf = feat + (size_t)(N_TOK + 3 * Dm) * Kf;
    const float* Rp = R + N_TOK + 3 * Dm;
    tversky64(cf, pf, Rcf, Rp, tab[9], tab[10], tab[11],
              blockIdx.y * 64, blockIdx.x * 64, out, Dm);
}

// ---------------- scores: S = Q @ K^T / 8, masked (scalar, balanced) --------
__global__ __launch_bounds__(256) void scores_kernel(
    const float* __restrict__ Q, const float* __restrict__ Km,
    const int* __restrict__ mask, float* __restrict__ scores)
{
    __shared__ float Qs[64][68];   // [d][m]
    __shared__ float Ks[64][68];
    int z = blockIdx.z;
    int b = z >> 3, h = z & 7;
    const float* Qg = Q  + (size_t)b * Sq * Dm + h * DK;
    const float* Kg = Km + (size_t)b * Sq * Dm + h * DK;
    int bq = blockIdx.y * 64, bk = blockIdx.x * 64;
    int tx = threadIdx.x, ty = threadIdx.y;
    int tid = ty * 16 + tx;
#pragma unroll
    for (int l = 0; l < 16; l++) {
        int e = tid + l * 256;
        int m = e >> 6, d = e & 63;
        Qs[d][m] = Qg[(size_t)(bq + m) * Dm + d];
        Ks[d][m] = Kg[(size_t)(bk + m) * Dm + d];
    }
    __syncthreads();
    float acc[4][4] = {};
#pragma unroll
    for (int d = 0; d < 64; d++) {
        float4 a4 = *(const float4*)&Qs[d][ty * 4];
        float4 b4 = *(const float4*)&Ks[d][tx * 4];
        float av[4] = {a4.x, a4.y, a4.z, a4.w};
        float bv[4] = {b4.x, b4.y, b4.z, b4.w};
#pragma unroll
        for (int i = 0; i < 4; i++)
#pragma unroll
            for (int j = 0; j < 4; j++)
                acc[i][j] = fmaf(av[i], bv[j], acc[i][j]);
    }
    float* sout = scores + (size_t)z * Sq * Sq;
    const int* mg = mask + (size_t)b * Sq * Sq;
#pragma unroll
    for (int i = 0; i < 4; i++)
#pragma unroll
        for (int j = 0; j < 4; j++) {
            int q = bq + ty * 4 + i, kk = bk + tx * 4 + j;
            float s = acc[i][j] * 0.125f;
            if (mg[(size_t)q * Sq + kk] == 0) s = -INFINITY;
            sout[(size_t)q * Sq + kk] = s;
        }
}

// ---------------- row softmax over 512 --------------------------------------
__global__ __launch_bounds__(128) void softmax_kernel(float* __restrict__ scores)
{
    __shared__ float red_m[4], red_s[4];
    size_t row = blockIdx.x;
    float* r = scores + row * Sq;
    int t = threadIdx.x;
    float v0 = r[t], v1 = r[t + 128], v2 = r[t + 256], v3 = r[t + 384];
    float m = fmaxf(fmaxf(v0, v1), fmaxf(v2, v3));
#pragma unroll
    for (int o = 16; o; o >>= 1) m = fmaxf(m, __shfl_xor_sync(0xffffffffu, m, o));
    if ((t & 31) == 0) red_m[t >> 5] = m;
    __syncthreads();
    m = fmaxf(fmaxf(red_m[0], red_m[1]), fmaxf(red_m[2], red_m[3]));
    float e0 = expf(v0 - m), e1 = expf(v1 - m), e2 = expf(v2 - m), e3 = expf(v3 - m);
    float s = e0 + e1 + e2 + e3;
#pragma unroll
    for (int o = 16; o; o >>= 1) s += __shfl_xor_sync(0xffffffffu, s, o);
    if ((t & 31) == 0) red_s[t >> 5] = s;
    __syncthreads();
    s = red_s[0] + red_s[1] + red_s[2] + red_s[3];
    float inv = 1.f / s;
    r[t]       = e0 * inv;
    r[t + 128] = e1 * inv;
    r[t + 256] = e2 * inv;
    r[t + 384] = e3 * inv;
}

// ---------------- ctx = attn @ V (per head, scalar) -------------------------
__global__ __launch_bounds__(256) void ctx_kernel(
    const float* __restrict__ scores, const float* __restrict__ V,
    float* __restrict__ ctx)
{
    __shared__ float As[32][68];   // [k][q]
    __shared__ float Bs[32][68];   // [k][d]
    int z = blockIdx.z;
    int b = z >> 3, h = z & 7;
    const float* Ag = scores + (size_t)z * Sq * Sq;
    const float* Vg = V + (size_t)b * Sq * Dm + h * DK;
    int bq = blockIdx.y * 64;
    int tx = threadIdx.x, ty = threadIdx.y;
    int tid = ty * 16 + tx;
    float acc[4][4] = {};
    for (int k0 = 0; k0 < Sq; k0 += 32) {
#pragma unroll
        for (int l = 0; l < 8; l++) {
            int e = tid + l * 256;
            int q = e >> 5, kk = e & 31;
            As[kk][q] = Ag[(size_t)(bq + q) * Sq + k0 + kk];
        }
#pragma unroll
        for (int l = 0; l < 8; l++) {
            int e = tid + l * 256;
            int kk = e >> 6, d = e & 63;
            Bs[kk][d] = Vg[(size_t)(k0 + kk) * Dm + d];
        }
        __syncthreads();
#pragma unroll
        for (int k = 0; k < 32; k++) {
            float4 a4 = *(const float4*)&As[k][ty * 4];
            float4 b4 = *(const float4*)&Bs[k][tx * 4];
            float av[4] = {a4.x, a4.y, a4.z, a4.w};
            float bv[4] = {b4.x, b4.y, b4.z, b4.w};
#pragma unroll
            for (int i = 0; i < 4; i++)
#pragma unroll
                for (int j = 0; j < 4; j++)
                    acc[i][j] = fmaf(av[i], bv[j], acc[i][j]);
        }
        __syncthreads();
    }
    float* cg = ctx + (size_t)b * Sq * Dm + h * DK;
#pragma unroll
    for (int i = 0; i < 4; i++)
#pragma unroll
        for (int j = 0; j < 4; j++)
            cg[(size_t)(bq + ty * 4 + i) * Dm + tx * 4 + j] = acc[i][j];
}

// ---------------- launch ----------------------------------------------------
extern "C" void kernel_launch(void* const* d_in, const int* in_sizes, int n_in,
                              void* d_out, int out_size)
{
    const float* x     = (const float*)d_in[0];
    const int*   mask  = (const int*)d_in[1];
    const float* omega = (const float*)d_in[2];
    const float* Pq    = (const float*)d_in[3];
    const float* Pk    = (const float*)d_in[4];
    const float* Pv    = (const float*)d_in[5];
    const float* Po    = (const float*)d_in[6];
    const float* tab   = (const float*)d_in[7];
    float* out = (float*)d_out;

    float *p_feat, *p_R, *p_Rcf, *p_qkv, *p_sc, *p_ctx, *p_cf;
    cudaGetSymbolAddress((void**)&p_feat, g_feat);
    cudaGetSymbolAddress((void**)&p_R, g_R);
    cudaGetSymbolAddress((void**)&p_Rcf, g_Rcf);
    cudaGetSymbolAddress((void**)&p_qkv, g_QKV);
    cudaGetSymbolAddress((void**)&p_sc, g_scores);
    cudaGetSymbolAddress((void**)&p_ctx, g_ctx);
    cudaGetSymbolAddress((void**)&p_cf, g_cf);

    float* p_Q = p_qkv;
    float* p_K = p_qkv + (size_t)N_TOK * Dm;
    float* p_V = p_qkv + (size_t)2 * N_TOK * Dm;

    dim3 blk(16, 16);
    dim3 tvb(16, 8);

    // feature maps + row relu-sums
    feat_gemm<<<dim3(2, 48), blk>>>(x, Pq, Pk, Pv, Po, omega, p_feat);
    rowrelu<<<(N_TOK + 4 * Dm) / 8, dim3(32, 8)>>>(p_feat, p_R);

    // Q, K, V projections (64x64 tiles, 128 threads)
    tversky_qkv<<<dim3(8, 16, 3), tvb>>>(p_feat, p_R, tab, p_qkv);

    // attention
    scores_kernel<<<dim3(8, 8, 16), blk>>>(p_Q, p_K, mask, p_sc);
    softmax_kernel<<<16 * Sq, 128>>>(p_sc);
    ctx_kernel<<<dim3(1, 8, 16), blk>>>(p_sc, p_V, p_ctx);

    // output projection
    gemm_nn<<<dim3(2, 16), blk>>>(p_ctx, omega, p_cf, N_TOK, Kf, Dm, Dm, Kf, Kf);
    rowrelu<<<N_TOK / 8, dim3(32, 8)>>>(p_cf, p_Rcf);
    tversky_out<<<dim3(8, 16), tvb>>>(p_cf, p_Rcf, p_feat, p_R, tab, out);
}